// round 15
// baseline (speedup 1.0000x reference)
#include <cuda_runtime.h>
#include <cuda_fp16.h>

#define N_NODES 100000
#define N_EDGES 1600000
#define FDIM 128
#define N_GRAPHS 256
#define NODE_ELEMS (N_NODES*FDIM)
#define NQ (NODE_ELEMS/4)          // 4-feature packets per node grid (32/node)
#define SCAN_B 1024
#define NBLK ((N_NODES + SCAN_B - 1)/SCAN_B)   // 98 (< 148 SMs: single wave)

// -------- scratch (static device globals; no allocation anywhere) --------
__device__ int      g_indeg[N_NODES];
__device__ int      g_off[N_NODES];
__device__ int      g_cur[N_NODES];
__device__ int      g_csr[N_EDGES];
__device__ float    g_dinv[N_NODES];
__device__ int      g_bsum[NBLK];
__device__ volatile int g_brdy[NBLK];
__device__ unsigned g_q0[NQ];        // 12.8 MB e4m3 features (hop1 input)
__device__ unsigned g_q1[NQ];        // 12.8 MB e4m3 features (hop1 out, x16 scaled)
__device__ uint2    g_h0[NQ];        // 25.6 MB fp16 features (hop2 out -> GEMM)
__device__ __half   g_Wh[FDIM*FDIM]; // W^T in fp16: g_Wh[c*128+f] = W[f][c]
__device__ float    g_pool[N_GRAPHS*FDIM];
__device__ int      g_cnt[N_GRAPHS];

__device__ __forceinline__ uint2 f4_to_h4(float4 v) {
    __half2 a = __floats2half2_rn(v.x, v.y);
    __half2 b = __floats2half2_rn(v.z, v.w);
    uint2 u;
    u.x = *(unsigned*)&a;
    u.y = *(unsigned*)&b;
    return u;
}
// position-preserving fp8 pack/unpack (via f16x2, so byte order is consistent)
__device__ __forceinline__ unsigned pack_e4m3(float4 v) {
    __half2 a = __floats2half2_rn(v.x, v.y);
    __half2 b = __floats2half2_rn(v.z, v.w);
    unsigned short qa, qb;
    asm("cvt.rn.satfinite.e4m3x2.f16x2 %0, %1;" : "=h"(qa) : "r"(*(unsigned*)&a));
    asm("cvt.rn.satfinite.e4m3x2.f16x2 %0, %1;" : "=h"(qb) : "r"(*(unsigned*)&b));
    return (unsigned)qa | ((unsigned)qb << 16);
}
__device__ __forceinline__ void unpack_e4m3(unsigned q, __half2& a, __half2& b) {
    unsigned ra, rb;
    unsigned short lo = (unsigned short)(q & 0xFFFFu);
    unsigned short hi = (unsigned short)(q >> 16);
    asm("cvt.rn.f16x2.e4m3x2 %0, %1;" : "=r"(ra) : "h"(lo));
    asm("cvt.rn.f16x2.e4m3x2 %0, %1;" : "=r"(rb) : "h"(hi));
    a = *(__half2*)&ra;
    b = *(__half2*)&rb;
}

// -------- fused init + W convert --------
__global__ void k_init_wcvt(const float* __restrict__ Wm) {
    int i = blockIdx.x * blockDim.x + threadIdx.x;
    if (i < N_NODES) g_indeg[i] = 0;
    if (i < N_GRAPHS*FDIM) g_pool[i] = 0.0f;
    if (i < N_GRAPHS) g_cnt[i] = 0;
    if (i < NBLK) g_brdy[i] = 0;
    if (i < FDIM*FDIM) {                 // W fp32 [f][c] -> fp16 transposed [c][f]
        int f = i >> 7, c = i & 127;
        g_Wh[c*FDIM + f] = __float2half(Wm[i]);
    }
}

// -------- degree histogram (int2, 2 edges/thread) + per-graph counts --------
#define E2 (N_EDGES/2)
__global__ void k_degree_cnt(const int* __restrict__ ei, const int* __restrict__ batch) {
    int p = blockIdx.x * blockDim.x + threadIdx.x;
    if (p < E2) {
        int2 d = ((const int2*)(ei + N_EDGES))[p];
        atomicAdd(&g_indeg[d.x], 1);
        atomicAdd(&g_indeg[d.y], 1);
    }
    if (p < N_NODES) atomicAdd(&g_cnt[batch[p]], 1);
}

// -------- single-kernel exclusive scan (decoupled lookback; 98 blocks = 1 wave) --------
__global__ void k_scan() {
    __shared__ int wsum[32];
    __shared__ int sboff;
    int b = blockIdx.x, t = threadIdx.x;
    int i = b * SCAN_B + t;
    int v = (i < N_NODES) ? g_indeg[i] : 0;

    // warp-level inclusive scan
    int xs = v;
    #pragma unroll
    for (int o = 1; o < 32; o <<= 1) {
        int y = __shfl_up_sync(0xffffffffu, xs, o);
        if ((t & 31) >= o) xs += y;
    }
    if ((t & 31) == 31) wsum[t >> 5] = xs;
    __syncthreads();
    if (t < 32) {
        int s = wsum[t];
        #pragma unroll
        for (int o = 1; o < 32; o <<= 1) {
            int y = __shfl_up_sync(0xffffffffu, s, o);
            if (t >= o) s += y;
        }
        wsum[t] = s;   // inclusive over warps; wsum[31] = block total
    }
    __syncthreads();

    // publish block sum, then look back over predecessors (warp 0)
    if (t == 0) {
        g_bsum[b] = wsum[31];
        __threadfence();
        g_brdy[b] = 1;
    }
    if (t < 32) {
        int acc = 0;
        for (int j = t; j < b; j += 32) {
            while (g_brdy[j] == 0) { }               // co-resident: no deadlock
            acc += *(volatile int*)&g_bsum[j];
        }
        #pragma unroll
        for (int o = 16; o; o >>= 1) acc += __shfl_xor_sync(0xffffffffu, acc, o);
        if (t == 0) sboff = acc;
    }
    __syncthreads();

    int base = sboff + ((t >= 32) ? wsum[(t >> 5) - 1] : 0);
    int excl = base + xs - v;
    if (i < N_NODES) {
        g_off[i] = excl;
        g_cur[i] = excl;
        g_dinv[i] = rsqrtf((float)(v + 1));
    }
}

// -------- fused CSR fill (2 edges/thread, int2) + fp8 feature convert --------
#define FILL_BLKS ((E2 + 255)/256)           // 3125
#define CVT_BLKS  ((NQ + 255)/256)           // 12500

__global__ void k_fill_cvt(const int* __restrict__ ei, const float* __restrict__ x) {
    int b = blockIdx.x;
    if (b < FILL_BLKS) {
        int p = b * 256 + threadIdx.x;
        if (p >= E2) return;
        int2 s = ((const int2*)ei)[p];
        int2 d = ((const int2*)(ei + N_EDGES))[p];
        int pos0 = atomicAdd(&g_cur[d.x], 1);
        g_csr[pos0] = s.x;
        int pos1 = atomicAdd(&g_cur[d.y], 1);
        g_csr[pos1] = s.y;
    } else {
        int i = (b - FILL_BLKS) * 256 + threadIdx.x;
        if (i >= NQ) return;
        float dd = g_dinv[i >> 5];
        float4 t = ((const float4*)x)[i];
        t.x *= dd; t.y *= dd; t.z *= dd; t.w *= dd;
        g_q0[i] = pack_e4m3(t);          // g0 = e4m3(dinv * x)
    }
}

// shared gather core: fp8 rows, fp16 pair accumulation, 8-deep unroll (R12 form)
__device__ __forceinline__ float4 hop_gather(const unsigned* __restrict__ in,
                                             int w, int lane) {
    __half2 acc0, acc1;
    unpack_e4m3(__ldg(&in[w * 32 + lane]), acc0, acc1);   // self loop
    int beg = g_off[w];
    int cnt = g_indeg[w];
    int i = 0;
    for (; i + 8 <= cnt; i += 8) {
        int s[8];
        #pragma unroll
        for (int j = 0; j < 8; j++) s[j] = __ldg(&g_csr[beg + i + j]);
        unsigned u[8];
        #pragma unroll
        for (int j = 0; j < 8; j++) u[j] = __ldg(&in[s[j] * 32 + lane]);
        #pragma unroll
        for (int j = 0; j < 8; j++) {
            __half2 a, c;
            unpack_e4m3(u[j], a, c);
            acc0 = __hadd2(acc0, a);
            acc1 = __hadd2(acc1, c);
        }
    }
    for (; i < cnt; i++) {
        int s0 = __ldg(&g_csr[beg + i]);
        __half2 a, c;
        unpack_e4m3(__ldg(&in[s0 * 32 + lane]), a, c);
        acc0 = __hadd2(acc0, a);
        acc1 = __hadd2(acc1, c);
    }
    float2 f0 = __half22float2(acc0);
    float2 f1 = __half22float2(acc1);
    return make_float4(f0.x, f0.y, f1.x, f1.y);
}

// hop1: q0 -> q1, store 16*dinv^2*(sum+self)  (x16 centers e4m3 range)
__global__ void k_hop1() {
    int w = (blockIdx.x * blockDim.x + threadIdx.x) >> 5;
    if (w >= N_NODES) return;
    int lane = threadIdx.x & 31;
    float4 acc = hop_gather(g_q0, w, lane);
    float d = g_dinv[w];
    float f = d * d * 16.0f;
    acc.x *= f; acc.y *= f; acc.z *= f; acc.w *= f;
    g_q1[w * 32 + lane] = pack_e4m3(acc);
}

// hop2: q1 -> h0 (fp16), store (dinv/16)*(sum+self)
__global__ void k_hop2() {
    int w = (blockIdx.x * blockDim.x + threadIdx.x) >> 5;
    if (w >= N_NODES) return;
    int lane = threadIdx.x & 31;
    float4 acc = hop_gather(g_q1, w, lane);
    float f = g_dinv[w] * 0.0625f;
    acc.x *= f; acc.y *= f; acc.z *= f; acc.w *= f;
    g_h0[w * 32 + lane] = f4_to_h4(acc);
}

// -------- tensor-core GEMM + pool: z = relu(h2@W + b); pool += z --------
#define GM_NODES 64
#define SAS 136
#define SWS 136
#define SMEM_A_BYTES (GM_NODES*SAS*2)
#define SMEM_W_BYTES (FDIM*SWS*2)
#define GEMM_SMEM (SMEM_A_BYTES + SMEM_W_BYTES + GM_NODES*4)

__device__ __forceinline__ void mma16816(float4& d, unsigned a0, unsigned a1,
                                         unsigned a2, unsigned a3,
                                         unsigned b0, unsigned b1) {
    asm volatile("mma.sync.aligned.m16n8k16.row.col.f32.f16.f16.f32 "
        "{%0,%1,%2,%3}, {%4,%5,%6,%7}, {%8,%9}, {%0,%1,%2,%3};"
        : "+f"(d.x), "+f"(d.y), "+f"(d.z), "+f"(d.w)
        : "r"(a0), "r"(a1), "r"(a2), "r"(a3), "r"(b0), "r"(b1));
}

__global__ __launch_bounds__(128, 2) void k_gemm_pool(
        const float* __restrict__ bias, const int* __restrict__ batch) {
    extern __shared__ char smem[];
    __half* sA = (__half*)smem;                       // [64][SAS]
    __half* sW = (__half*)(smem + SMEM_A_BYTES);      // [128][SWS] (W^T: [n][k])
    float*  sO = (float*)smem;                        // overlay [64][128]
    int*    sB = (int*)(smem + SMEM_A_BYTES + SMEM_W_BYTES);
    int tid = threadIdx.x;
    int base = blockIdx.x * GM_NODES;

    for (int i = tid; i < GM_NODES*32; i += 128) {
        int r = i >> 5, q = i & 31;
        int node = base + r;
        uint2 u = make_uint2(0u, 0u);
        if (node < N_NODES) u = g_h0[node*32 + q];
        *(uint2*)&sA[r*SAS + q*4] = u;
    }
    for (int i = tid; i < FDIM*32; i += 128) {
        int r = i >> 5, q = i & 31;
        uint2 u = *(const uint2*)&g_Wh[r*FDIM + q*4];
        *(uint2*)&sW[r*SWS + q*4] = u;
    }
    if (tid < GM_NODES) {
        int node = base + tid;
        sB[tid] = (node < N_NODES) ? batch[node] : -1;
    }
    __syncthreads();

    int warp = tid >> 5, lane = tid & 31;
    int gid = lane >> 2, tig = lane & 3;
    int m0 = warp * 16;

    float4 acc[16];
    #pragma unroll
    for (int t = 0; t < 16; t++) acc[t] = make_float4(0.f, 0.f, 0.f, 0.f);

    #pragma unroll
    for (int k0 = 0; k0 < FDIM; k0 += 16) {
        unsigned a0 = *(unsigned*)&sA[(m0+gid)  *SAS + k0 + tig*2];
        unsigned a1 = *(unsigned*)&sA[(m0+gid+8)*SAS + k0 + tig*2];
        unsigned a2 = *(unsigned*)&sA[(m0+gid)  *SAS + k0 + tig*2 + 8];
        unsigned a3 = *(unsigned*)&sA[(m0+gid+8)*SAS + k0 + tig*2 + 8];
        #pragma unroll
        for (int t = 0; t < 16; t++) {
            int n0 = t * 8;
            unsigned b0 = *(unsigned*)&sW[(n0+gid)*SWS + k0 + tig*2];
            unsigned b1 = *(unsigned*)&sW[(n0+gid)*SWS + k0 + tig*2 + 8];
            mma16816(acc[t], a0, a1, a2, a3, b0, b1);
        }
    }

    __syncthreads();   // all A/W reads done before overlay writes
    #pragma unroll
    for (int t = 0; t < 16; t++) {
        int n0 = t * 8;
        sO[(m0+gid)  *FDIM + n0 + tig*2]     = acc[t].x;
        sO[(m0+gid)  *FDIM + n0 + tig*2 + 1] = acc[t].y;
        sO[(m0+gid+8)*FDIM + n0 + tig*2]     = acc[t].z;
        sO[(m0+gid+8)*FDIM + n0 + tig*2 + 1] = acc[t].w;
    }
    __syncwarp();      // each warp reads only its own 16 rows

    float4 bv = *(const float4*)&bias[lane*4];
    float4 run = make_float4(0.f, 0.f, 0.f, 0.f);
    int cur_gid = -1;
    #pragma unroll
    for (int n = 0; n < 16; n++) {
        int row = m0 + n;
        int gidn = sB[row];
        float4 a = *(float4*)&sO[row*FDIM + lane*4];
        float4 r;
        r.x = fmaxf(a.x + bv.x, 0.0f);
        r.y = fmaxf(a.y + bv.y, 0.0f);
        r.z = fmaxf(a.z + bv.z, 0.0f);
        r.w = fmaxf(a.w + bv.w, 0.0f);
        if (gidn != cur_gid) {
            if (cur_gid >= 0) {
                float* p = g_pool + cur_gid*FDIM + lane*4;
                atomicAdd(p+0, run.x); atomicAdd(p+1, run.y);
                atomicAdd(p+2, run.z); atomicAdd(p+3, run.w);
            }
            cur_gid = gidn;
            run = r;
        } else {
            run.x += r.x; run.y += r.y; run.z += r.z; run.w += r.w;
        }
    }
    if (cur_gid >= 0) {
        float* p = g_pool + cur_gid*FDIM + lane*4;
        atomicAdd(p+0, run.x); atomicAdd(p+1, run.y);
        atomicAdd(p+2, run.z); atomicAdd(p+3, run.w);
    }
}

// -------- mean + log_softmax, one block (128 threads) per graph --------
__global__ void k_softmax(float* __restrict__ out) {
    int g = blockIdx.x;
    int t = threadIdx.x;
    __shared__ float sm[4], ss[4];
    float c = fmaxf((float)g_cnt[g], 1.0f);
    float v = g_pool[g*FDIM + t] / c;
    float m = v;
    #pragma unroll
    for (int o = 16; o; o >>= 1) m = fmaxf(m, __shfl_xor_sync(0xffffffffu, m, o));
    if ((t & 31) == 0) sm[t >> 5] = m;
    __syncthreads();
    m = fmaxf(fmaxf(sm[0], sm[1]), fmaxf(sm[2], sm[3]));
    float e = expf(v - m);
    float s = e;
    #pragma unroll
    for (int o = 16; o; o >>= 1) s += __shfl_xor_sync(0xffffffffu, s, o);
    if ((t & 31) == 0) ss[t >> 5] = s;
    __syncthreads();
    s = ss[0] + ss[1] + ss[2] + ss[3];
    out[g*FDIM + t] = v - m - logf(s);
}

extern "C" void kernel_launch(void* const* d_in, const int* in_sizes, int n_in,
                              void* d_out, int out_size) {
    const float* x     = (const float*)d_in[0];
    const int*   ei    = (const int*)d_in[1];
    const int*   batch = (const int*)d_in[2];
    const float* Wm    = (const float*)d_in[3];
    const float* bias  = (const float*)d_in[4];
    float*       out   = (float*)d_out;

    cudaFuncSetAttribute(k_gemm_pool, cudaFuncAttributeMaxDynamicSharedMemorySize, GEMM_SMEM);

    k_init_wcvt  <<<(N_NODES + 255) / 256, 256>>>(Wm);
    k_degree_cnt <<<(E2 + 255) / 256, 256>>>(ei, batch);
    k_scan       <<<NBLK, SCAN_B>>>();
    k_fill_cvt   <<<FILL_BLKS + CVT_BLKS, 256>>>(ei, x);
    k_hop1       <<<(N_NODES * 32 + 255) / 256, 256>>>();  // q0 -> q1 (fp8)
    k_hop2       <<<(N_NODES * 32 + 255) / 256, 256>>>();  // q1 -> h0 (fp16)
    k_gemm_pool  <<<(N_NODES + GM_NODES - 1) / GM_NODES, 128, GEMM_SMEM>>>(bias, batch);
    k_softmax    <<<N_GRAPHS, FDIM>>>(out);
}

// round 16
// speedup vs baseline: 1.0551x; 1.0551x over previous
#include <cuda_runtime.h>
#include <cuda_fp16.h>

#define N_NODES 100000
#define N_EDGES 1600000
#define FDIM 128
#define N_GRAPHS 256
#define NODE_ELEMS (N_NODES*FDIM)
#define NQ (NODE_ELEMS/4)          // 4-feature packets per node grid (32/node)
#define SCAN_B 1024
#define NBLK ((N_NODES + SCAN_B - 1)/SCAN_B)   // 98

// -------- scratch (static device globals; no allocation anywhere) --------
__device__ int      g_indeg[N_NODES];
__device__ int      g_off[N_NODES];
__device__ int      g_cur[N_NODES];
__device__ int      g_csr[N_EDGES];
__device__ float    g_dinv[N_NODES];
__device__ int      g_bsum[NBLK];
__device__ unsigned g_q0[NQ];        // 12.8 MB e4m3 features (hop1 input)
__device__ unsigned g_q1[NQ];        // 12.8 MB e4m3 features (hop1 out, x16 scaled)
__device__ uint2    g_h0[NQ];        // 25.6 MB fp16 features (hop2 out -> GEMM)
__device__ __half   g_Wh[FDIM*FDIM]; // W^T in fp16: g_Wh[c*128+f] = W[f][c]
__device__ float    g_pool[N_GRAPHS*FDIM];
__device__ int      g_cnt[N_GRAPHS];

__device__ __forceinline__ uint2 f4_to_h4(float4 v) {
    __half2 a = __floats2half2_rn(v.x, v.y);
    __half2 b = __floats2half2_rn(v.z, v.w);
    uint2 u;
    u.x = *(unsigned*)&a;
    u.y = *(unsigned*)&b;
    return u;
}
// position-preserving fp8 pack/unpack (via f16x2, so byte order is consistent)
__device__ __forceinline__ unsigned pack_e4m3(float4 v) {
    __half2 a = __floats2half2_rn(v.x, v.y);
    __half2 b = __floats2half2_rn(v.z, v.w);
    unsigned short qa, qb;
    asm("cvt.rn.satfinite.e4m3x2.f16x2 %0, %1;" : "=h"(qa) : "r"(*(unsigned*)&a));
    asm("cvt.rn.satfinite.e4m3x2.f16x2 %0, %1;" : "=h"(qb) : "r"(*(unsigned*)&b));
    return (unsigned)qa | ((unsigned)qb << 16);
}
__device__ __forceinline__ void unpack_e4m3(unsigned q, __half2& a, __half2& b) {
    unsigned ra, rb;
    unsigned short lo = (unsigned short)(q & 0xFFFFu);
    unsigned short hi = (unsigned short)(q >> 16);
    asm("cvt.rn.f16x2.e4m3x2 %0, %1;" : "=r"(ra) : "h"(lo));
    asm("cvt.rn.f16x2.e4m3x2 %0, %1;" : "=r"(rb) : "h"(hi));
    a = *(__half2*)&ra;
    b = *(__half2*)&rb;
}

// -------- fused init + W convert --------
__global__ void k_init_wcvt(const float* __restrict__ Wm) {
    int i = blockIdx.x * blockDim.x + threadIdx.x;
    if (i < N_NODES) g_indeg[i] = 0;
    if (i < N_GRAPHS*FDIM) g_pool[i] = 0.0f;
    if (i < N_GRAPHS) g_cnt[i] = 0;
    if (i < FDIM*FDIM) {                 // W fp32 [f][c] -> fp16 transposed [c][f]
        int f = i >> 7, c = i & 127;
        g_Wh[c*FDIM + f] = __float2half(Wm[i]);
    }
}

// -------- degree histogram + per-graph node counts (folded) --------
__global__ void k_degree_cnt(const int* __restrict__ ei, const int* __restrict__ batch) {
    int e = blockIdx.x * blockDim.x + threadIdx.x;
    if (e < N_EDGES) atomicAdd(&g_indeg[ei[N_EDGES + e]], 1);
    if (e < N_NODES) atomicAdd(&g_cnt[batch[e]], 1);
}

// -------- 2-phase coalesced exclusive scan of indegrees --------
__global__ void k_scan1() {
    __shared__ int sh[32];
    int b = blockIdx.x, t = threadIdx.x;
    int i = b * SCAN_B + t;
    int v = (i < N_NODES) ? g_indeg[i] : 0;
    #pragma unroll
    for (int o = 16; o; o >>= 1) v += __shfl_xor_sync(0xffffffffu, v, o);
    if ((t & 31) == 0) sh[t >> 5] = v;
    __syncthreads();
    if (t < 32) {
        int s = sh[t];
        #pragma unroll
        for (int o = 16; o; o >>= 1) s += __shfl_xor_sync(0xffffffffu, s, o);
        if (t == 0) g_bsum[b] = s;
    }
}

// block-local scan; warp 0 sums prior block-sums in parallel
__global__ void k_scan3() {
    __shared__ int wsum[32];
    __shared__ int sboff;
    int b = blockIdx.x, t = threadIdx.x;
    if (t < 32) {
        int acc = 0;
        for (int j = t; j < b; j += 32) acc += g_bsum[j];
        #pragma unroll
        for (int o = 16; o; o >>= 1) acc += __shfl_xor_sync(0xffffffffu, acc, o);
        if (t == 0) sboff = acc;
    }
    int i = b * SCAN_B + t;
    int v = (i < N_NODES) ? g_indeg[i] : 0;
    int xs = v;
    #pragma unroll
    for (int o = 1; o < 32; o <<= 1) {
        int y = __shfl_up_sync(0xffffffffu, xs, o);
        if ((t & 31) >= o) xs += y;
    }
    if ((t & 31) == 31) wsum[t >> 5] = xs;
    __syncthreads();
    if (t < 32) {
        int s = wsum[t];
        #pragma unroll
        for (int o = 1; o < 32; o <<= 1) {
            int y = __shfl_up_sync(0xffffffffu, s, o);
            if (t >= o) s += y;
        }
        wsum[t] = s;   // inclusive over warps
    }
    __syncthreads();
    int base = sboff + ((t >= 32) ? wsum[(t >> 5) - 1] : 0);
    int excl = base + xs - v;
    if (i < N_NODES) {
        g_off[i] = excl;
        g_cur[i] = excl;
        g_dinv[i] = rsqrtf((float)(v + 1));
    }
}

// -------- fused CSR fill (2 edges/thread, int2) + fp8 feature convert --------
#define E2 (N_EDGES/2)
#define FILL_BLKS ((E2 + 255)/256)           // 3125
#define CVT_BLKS  ((NQ + 255)/256)           // 12500

__global__ void k_fill_cvt(const int* __restrict__ ei, const float* __restrict__ x) {
    int b = blockIdx.x;
    if (b < FILL_BLKS) {
        int p = b * 256 + threadIdx.x;
        if (p >= E2) return;
        int2 s = ((const int2*)ei)[p];
        int2 d = ((const int2*)(ei + N_EDGES))[p];
        int pos0 = atomicAdd(&g_cur[d.x], 1);
        g_csr[pos0] = s.x;
        int pos1 = atomicAdd(&g_cur[d.y], 1);
        g_csr[pos1] = s.y;
    } else {
        int i = (b - FILL_BLKS) * 256 + threadIdx.x;
        if (i >= NQ) return;
        float dd = g_dinv[i >> 5];
        float4 t = ((const float4*)x)[i];
        t.x *= dd; t.y *= dd; t.z *= dd; t.w *= dd;
        g_q0[i] = pack_e4m3(t);          // g0 = e4m3(dinv * x)
    }
}

// shared gather core: fp8 rows, fp16 pair accumulation, 8-deep unroll
__device__ __forceinline__ float4 hop_gather(const unsigned* __restrict__ in,
                                             int w, int lane) {
    __half2 acc0, acc1;
    unpack_e4m3(__ldg(&in[w * 32 + lane]), acc0, acc1);   // self loop
    int beg = g_off[w];
    int cnt = g_indeg[w];
    int i = 0;
    for (; i + 8 <= cnt; i += 8) {
        int s[8];
        #pragma unroll
        for (int j = 0; j < 8; j++) s[j] = __ldg(&g_csr[beg + i + j]);
        unsigned u[8];
        #pragma unroll
        for (int j = 0; j < 8; j++) u[j] = __ldg(&in[s[j] * 32 + lane]);
        #pragma unroll
        for (int j = 0; j < 8; j++) {
            __half2 a, c;
            unpack_e4m3(u[j], a, c);
            acc0 = __hadd2(acc0, a);
            acc1 = __hadd2(acc1, c);
        }
    }
    for (; i < cnt; i++) {
        int s0 = __ldg(&g_csr[beg + i]);
        __half2 a, c;
        unpack_e4m3(__ldg(&in[s0 * 32 + lane]), a, c);
        acc0 = __hadd2(acc0, a);
        acc1 = __hadd2(acc1, c);
    }
    float2 f0 = __half22float2(acc0);
    float2 f1 = __half22float2(acc1);
    return make_float4(f0.x, f0.y, f1.x, f1.y);
}

// hop1: q0 -> q1, store 16*dinv^2*(sum+self)  (x16 centers e4m3 range)
__global__ void k_hop1() {
    int w = (blockIdx.x * blockDim.x + threadIdx.x) >> 5;
    if (w >= N_NODES) return;
    int lane = threadIdx.x & 31;
    float4 acc = hop_gather(g_q0, w, lane);
    float d = g_dinv[w];
    float f = d * d * 16.0f;
    acc.x *= f; acc.y *= f; acc.z *= f; acc.w *= f;
    g_q1[w * 32 + lane] = pack_e4m3(acc);
}

// hop2: q1 -> h0 (fp16), store (dinv/16)*(sum+self)
__global__ void k_hop2() {
    int w = (blockIdx.x * blockDim.x + threadIdx.x) >> 5;
    if (w >= N_NODES) return;
    int lane = threadIdx.x & 31;
    float4 acc = hop_gather(g_q1, w, lane);
    float f = g_dinv[w] * 0.0625f;
    acc.x *= f; acc.y *= f; acc.z *= f; acc.w *= f;
    g_h0[w * 32 + lane] = f4_to_h4(acc);
}

// -------- tensor-core GEMM + pool: z = relu(h2@W + b); pool += z --------
#define GM_NODES 64
#define SAS 136
#define SWS 136
#define SMEM_A_BYTES (GM_NODES*SAS*2)
#define SMEM_W_BYTES (FDIM*SWS*2)
#define GEMM_SMEM (SMEM_A_BYTES + SMEM_W_BYTES + GM_NODES*4)

__device__ __forceinline__ void mma16816(float4& d, unsigned a0, unsigned a1,
                                         unsigned a2, unsigned a3,
                                         unsigned b0, unsigned b1) {
    asm volatile("mma.sync.aligned.m16n8k16.row.col.f32.f16.f16.f32 "
        "{%0,%1,%2,%3}, {%4,%5,%6,%7}, {%8,%9}, {%0,%1,%2,%3};"
        : "+f"(d.x), "+f"(d.y), "+f"(d.z), "+f"(d.w)
        : "r"(a0), "r"(a1), "r"(a2), "r"(a3), "r"(b0), "r"(b1));
}

__global__ __launch_bounds__(128, 2) void k_gemm_pool(
        const float* __restrict__ bias, const int* __restrict__ batch) {
    extern __shared__ char smem[];
    __half* sA = (__half*)smem;                       // [64][SAS]
    __half* sW = (__half*)(smem + SMEM_A_BYTES);      // [128][SWS] (W^T: [n][k])
    float*  sO = (float*)smem;                        // overlay [64][128]
    int*    sB = (int*)(smem + SMEM_A_BYTES + SMEM_W_BYTES);
    int tid = threadIdx.x;
    int base = blockIdx.x * GM_NODES;

    for (int i = tid; i < GM_NODES*32; i += 128) {
        int r = i >> 5, q = i & 31;
        int node = base + r;
        uint2 u = make_uint2(0u, 0u);
        if (node < N_NODES) u = g_h0[node*32 + q];
        *(uint2*)&sA[r*SAS + q*4] = u;
    }
    for (int i = tid; i < FDIM*32; i += 128) {
        int r = i >> 5, q = i & 31;
        uint2 u = *(const uint2*)&g_Wh[r*FDIM + q*4];
        *(uint2*)&sW[r*SWS + q*4] = u;
    }
    if (tid < GM_NODES) {
        int node = base + tid;
        sB[tid] = (node < N_NODES) ? batch[node] : -1;
    }
    __syncthreads();

    int warp = tid >> 5, lane = tid & 31;
    int gid = lane >> 2, tig = lane & 3;
    int m0 = warp * 16;

    float4 acc[16];
    #pragma unroll
    for (int t = 0; t < 16; t++) acc[t] = make_float4(0.f, 0.f, 0.f, 0.f);

    #pragma unroll
    for (int k0 = 0; k0 < FDIM; k0 += 16) {
        unsigned a0 = *(unsigned*)&sA[(m0+gid)  *SAS + k0 + tig*2];
        unsigned a1 = *(unsigned*)&sA[(m0+gid+8)*SAS + k0 + tig*2];
        unsigned a2 = *(unsigned*)&sA[(m0+gid)  *SAS + k0 + tig*2 + 8];
        unsigned a3 = *(unsigned*)&sA[(m0+gid+8)*SAS + k0 + tig*2 + 8];
        #pragma unroll
        for (int t = 0; t < 16; t++) {
            int n0 = t * 8;
            unsigned b0 = *(unsigned*)&sW[(n0+gid)*SWS + k0 + tig*2];
            unsigned b1 = *(unsigned*)&sW[(n0+gid)*SWS + k0 + tig*2 + 8];
            mma16816(acc[t], a0, a1, a2, a3, b0, b1);
        }
    }

    __syncthreads();   // all A/W reads done before overlay writes
    #pragma unroll
    for (int t = 0; t < 16; t++) {
        int n0 = t * 8;
        sO[(m0+gid)  *FDIM + n0 + tig*2]     = acc[t].x;
        sO[(m0+gid)  *FDIM + n0 + tig*2 + 1] = acc[t].y;
        sO[(m0+gid+8)*FDIM + n0 + tig*2]     = acc[t].z;
        sO[(m0+gid+8)*FDIM + n0 + tig*2 + 1] = acc[t].w;
    }
    __syncwarp();      // each warp reads only its own 16 rows

    float4 bv = *(const float4*)&bias[lane*4];
    float4 run = make_float4(0.f, 0.f, 0.f, 0.f);
    int cur_gid = -1;
    #pragma unroll
    for (int n = 0; n < 16; n++) {
        int row = m0 + n;
        int gidn = sB[row];
        float4 a = *(float4*)&sO[row*FDIM + lane*4];
        float4 r;
        r.x = fmaxf(a.x + bv.x, 0.0f);
        r.y = fmaxf(a.y + bv.y, 0.0f);
        r.z = fmaxf(a.z + bv.z, 0.0f);
        r.w = fmaxf(a.w + bv.w, 0.0f);
        if (gidn != cur_gid) {
            if (cur_gid >= 0) {
                float* p = g_pool + cur_gid*FDIM + lane*4;
                atomicAdd(p+0, run.x); atomicAdd(p+1, run.y);
                atomicAdd(p+2, run.z); atomicAdd(p+3, run.w);
            }
            cur_gid = gidn;
            run = r;
        } else {
            run.x += r.x; run.y += r.y; run.z += r.z; run.w += r.w;
        }
    }
    if (cur_gid >= 0) {
        float* p = g_pool + cur_gid*FDIM + lane*4;
        atomicAdd(p+0, run.x); atomicAdd(p+1, run.y);
        atomicAdd(p+2, run.z); atomicAdd(p+3, run.w);
    }
}

// -------- mean + log_softmax, one block (128 threads) per graph --------
__global__ void k_softmax(float* __restrict__ out) {
    int g = blockIdx.x;
    int t = threadIdx.x;
    __shared__ float sm[4], ss[4];
    float c = fmaxf((float)g_cnt[g], 1.0f);
    float v = g_pool[g*FDIM + t] / c;
    float m = v;
    #pragma unroll
    for (int o = 16; o; o >>= 1) m = fmaxf(m, __shfl_xor_sync(0xffffffffu, m, o));
    if ((t & 31) == 0) sm[t >> 5] = m;
    __syncthreads();
    m = fmaxf(fmaxf(sm[0], sm[1]), fmaxf(sm[2], sm[3]));
    float e = expf(v - m);
    float s = e;
    #pragma unroll
    for (int o = 16; o; o >>= 1) s += __shfl_xor_sync(0xffffffffu, s, o);
    if ((t & 31) == 0) ss[t >> 5] = s;
    __syncthreads();
    s = ss[0] + ss[1] + ss[2] + ss[3];
    out[g*FDIM + t] = v - m - logf(s);
}

extern "C" void kernel_launch(void* const* d_in, const int* in_sizes, int n_in,
                              void* d_out, int out_size) {
    const float* x     = (const float*)d_in[0];
    const int*   ei    = (const int*)d_in[1];
    const int*   batch = (const int*)d_in[2];
    const float* Wm    = (const float*)d_in[3];
    const float* bias  = (const float*)d_in[4];
    float*       out   = (float*)d_out;

    cudaFuncSetAttribute(k_gemm_pool, cudaFuncAttributeMaxDynamicSharedMemorySize, GEMM_SMEM);

    k_init_wcvt  <<<(N_NODES + 255) / 256, 256>>>(Wm);
    k_degree_cnt <<<(N_EDGES + 255) / 256, 256>>>(ei, batch);
    k_scan1      <<<NBLK, SCAN_B>>>();
    k_scan3      <<<NBLK, SCAN_B>>>();
    k_fill_cvt   <<<FILL_BLKS + CVT_BLKS, 256>>>(ei, x);
    k_hop1       <<<(N_NODES * 32 + 255) / 256, 256>>>();  // q0 -> q1 (fp8)
    k_hop2       <<<(N_NODES * 32 + 255) / 256, 256>>>();  // q1 -> h0 (fp16)
    k_gemm_pool  <<<(N_NODES + GM_NODES - 1) / GM_NODES, 128, GEMM_SMEM>>>(bias, batch);
    k_softmax    <<<N_GRAPHS, FDIM>>>(out);
}